// round 12
// baseline (speedup 1.0000x reference)
#include <cuda_runtime.h>
#include <cuda_bf16.h>

#define VOCAB 50000
#define D 256
#define E 20000
#define L 20

// ---------------- scratch (static device globals; no allocation) ----------------
__device__ float g_qemb[D];
__device__ float g_g0[D];        // alpha(d) * qemb[d]
__device__ float g_g1[D];        // beta(d)  * qemb[d]
__device__ float g_u[VOCAB];
__device__ float g_w[VOCAB];
__device__ __align__(16) float g_A[VOCAB];  // unnormalized attention mass per vocab id
__device__ __align__(16) float g_B[VOCAB];  // same, weighted by l/L
__device__ float g_accA[D];
__device__ float g_accB[D];
__device__ float g_wte1[D];
__device__ float g_sumw;         // sum of exp(scores)
__device__ float g_sumexp;       // sum of exp(logits)

__device__ __forceinline__ float warp_sum(float v) {
    #pragma unroll
    for (int o = 16; o > 0; o >>= 1) v += __shfl_xor_sync(0xffffffffu, v, o);
    return v;
}

__device__ __forceinline__ float dot8(float4 x0, float4 x1, float4 c0, float4 c1) {
    return x0.x*c0.x + x0.y*c0.y + x0.z*c0.z + x0.w*c0.w
         + x1.x*c1.x + x1.y*c1.y + x1.z*c1.z + x1.w*c1.w;
}

// ---------------- K1: q_emb + derived vectors, zero accumulators ----------------
__global__ void k1_qemb(const int* __restrict__ question,
                        const float* __restrict__ q_table) {
    int d = threadIdx.x;                         // 256 threads
    float a  = 1.0f - (float)d * (1.0f / D);
    float be = 2.0f * (float)d * (1.0f / D) - 1.0f;
    float s = 0.0f;
    #pragma unroll
    for (int l = 0; l < L; ++l) {
        int v = question[l];
        float pe = a + ((float)l * (1.0f / L)) * be;
        s += __ldg(&q_table[(size_t)v * D + d]) * pe;
    }
    g_qemb[d] = s;
    g_g0[d] = a * s;
    g_g1[d] = be * s;
    g_accA[d] = 0.0f; g_accB[d] = 0.0f; g_wte1[d] = 0.0f;
    if (d == 0) { g_sumw = 0.0f; g_sumexp = 0.0f; }
}

// ---------------- K2: u[v], w[v] over q_table; zero A/B --------------------------
// 2 rows per warp, 16 rows/block, grid 3125. 4 independent one-shot LDG.128.
__global__ void k2_uw(const float* __restrict__ q_table) {
    __shared__ float4 s0[64], s1[64];
    int t = threadIdx.x;                      // 256
    if (t < 64) {
        s0[t] = ((const float4*)g_g0)[t];
        s1[t] = ((const float4*)g_g1)[t];
    }
    __syncthreads();
    int warp = t >> 5, lane = t & 31;
    int vbase = blockIdx.x * 16 + warp * 2;
    const float4* rowA = (const float4*)(q_table + (size_t)vbase * D);
    const float4* rowB = (const float4*)(q_table + (size_t)(vbase + 1) * D);
    float4 xa0 = __ldg(&rowA[lane]);
    float4 xa1 = __ldg(&rowA[lane + 32]);
    float4 xb0 = __ldg(&rowB[lane]);
    float4 xb1 = __ldg(&rowB[lane + 32]);
    float4 c0 = s0[lane], c1 = s0[lane + 32];
    float4 d0 = s1[lane], d1 = s1[lane + 32];
    float u0 = dot8(xa0, xa1, c0, c1);
    float w0 = dot8(xa0, xa1, d0, d1);
    float u1 = dot8(xb0, xb1, c0, c1);
    float w1 = dot8(xb0, xb1, d0, d1);
    u0 = warp_sum(u0); w0 = warp_sum(w0);
    u1 = warp_sum(u1); w1 = warp_sum(w1);
    if (lane == 0) {
        g_u[vbase] = u0;     g_w[vbase] = w0;
        g_u[vbase + 1] = u1; g_w[vbase + 1] = w1;
    }
    if (t < 16) { g_A[blockIdx.x * 16 + t] = 0.0f; g_B[blockIdx.x * 16 + t] = 0.0f; }
}

// ---------------- K34: fused scores + exp + A/B scatter + weights@te1 ------------
#define K34_CHUNK  32
#define K34_BLOCKS (E / K34_CHUNK)    // 625
__global__ void k34_weights(const int* __restrict__ evidence,
                            const float* __restrict__ te2,
                            const float* __restrict__ te1) {
    __shared__ float4 sq[64];
    __shared__ float s_w[K34_CHUNK];
    int t = threadIdx.x;                      // 256
    int warp = t >> 5, lane = t & 31;
    if (t < 64) sq[t] = ((const float4*)g_qemb)[t];
    __syncthreads();
    int e0 = blockIdx.x * K34_CHUNK;
    float4 q0 = sq[lane], q1 = sq[lane + 32];
    float part[4];
    #pragma unroll
    for (int r = 0; r < 4; ++r) {
        int e = e0 + warp * 4 + r;
        float p = 0.0f;
        if (lane < L) {
            int v = __ldg(&evidence[e * L + lane]);
            p = g_u[v] + ((float)lane * (1.0f / L)) * g_w[v];
        }
        const float4* row = (const float4*)(te2 + (size_t)e * D);
        float4 x0 = __ldg(&row[lane]);
        float4 x1 = __ldg(&row[lane + 32]);
        part[r] = p + dot8(x0, x1, q0, q1);
    }
    #pragma unroll
    for (int r = 0; r < 4; ++r) part[r] = warp_sum(part[r]);
    if (lane == 0) {
        #pragma unroll
        for (int r = 0; r < 4; ++r) s_w[warp * 4 + r] = part[r];
    }
    __syncthreads();
    if (t < 32) {
        float w = expf(s_w[t]);
        s_w[t] = w;
        float s = warp_sum(w);
        if (t == 0) atomicAdd(&g_sumw, s);
    }
    __syncthreads();
    for (int i = t; i < K34_CHUNK * L; i += 256) {
        int el = i / L;
        int l  = i - el * L;
        int v  = __ldg(&evidence[(e0 + el) * L + l]);
        float w = s_w[el];
        atomicAdd(&g_A[v], w);
        atomicAdd(&g_B[v], w * ((float)l * (1.0f / L)));
    }
    int d = t;
    float acc = 0.0f;
    #pragma unroll 8
    for (int el = 0; el < K34_CHUNK; ++el)
        acc += s_w[el] * __ldg(&te1[(size_t)(e0 + el) * D + d]);
    atomicAdd(&g_wte1[d], acc);
}

// ---------------- K5: accA/accB = A@e_table, B@e_table (ONE-SHOT blocks) ---------
// grid 3125, each block owns contiguous 16 rows (16KB). Thread t: float4 column
// col4=t&63, row-group r0=t>>6; loads 4 independent LDG.128 (rows r0+4k) in one
// shot -- the exact load shape proven fast in k2. Smem row-group reduce + atomics.
#define K5_BLOCKS (VOCAB / 16)       // 3125
__global__ void k5_etable(const float* __restrict__ e_table) {
    __shared__ float4 s_a[4][64];
    __shared__ float4 s_b[4][64];
    int t = threadIdx.x;                      // 256
    int col4 = t & 63, r0 = t >> 6;
    int v0 = blockIdx.x * 16;
    const float4* src = (const float4*)e_table + (size_t)v0 * 64;
    float4 x0 = __ldg(src + t);               // row r0,    col col4
    float4 x1 = __ldg(src + t + 256);         // row r0+4
    float4 x2 = __ldg(src + t + 512);         // row r0+8
    float4 x3 = __ldg(src + t + 768);         // row r0+12
    float A0 = __ldg(&g_A[v0 + r0]);
    float A1 = __ldg(&g_A[v0 + r0 + 4]);
    float A2 = __ldg(&g_A[v0 + r0 + 8]);
    float A3 = __ldg(&g_A[v0 + r0 + 12]);
    float B0 = __ldg(&g_B[v0 + r0]);
    float B1 = __ldg(&g_B[v0 + r0 + 4]);
    float B2 = __ldg(&g_B[v0 + r0 + 8]);
    float B3 = __ldg(&g_B[v0 + r0 + 12]);
    float4 a, b;
    a.x = A0*x0.x + A1*x1.x + A2*x2.x + A3*x3.x;
    a.y = A0*x0.y + A1*x1.y + A2*x2.y + A3*x3.y;
    a.z = A0*x0.z + A1*x1.z + A2*x2.z + A3*x3.z;
    a.w = A0*x0.w + A1*x1.w + A2*x2.w + A3*x3.w;
    b.x = B0*x0.x + B1*x1.x + B2*x2.x + B3*x3.x;
    b.y = B0*x0.y + B1*x1.y + B2*x2.y + B3*x3.y;
    b.z = B0*x0.z + B1*x1.z + B2*x2.z + B3*x3.z;
    b.w = B0*x0.w + B1*x1.w + B2*x2.w + B3*x3.w;
    s_a[r0][col4] = a; s_b[r0][col4] = b;
    __syncthreads();
    if (r0 == 0) {
        float4 a1 = s_a[1][col4], a2 = s_a[2][col4], a3 = s_a[3][col4];
        float4 b1 = s_b[1][col4], b2 = s_b[2][col4], b3 = s_b[3][col4];
        a.x += a1.x + a2.x + a3.x; a.y += a1.y + a2.y + a3.y;
        a.z += a1.z + a2.z + a3.z; a.w += a1.w + a2.w + a3.w;
        b.x += b1.x + b2.x + b3.x; b.y += b1.y + b2.y + b3.y;
        b.z += b1.z + b2.z + b3.z; b.w += b1.w + b2.w + b3.w;
        int d = col4 * 4;
        atomicAdd(&g_accA[d + 0], a.x); atomicAdd(&g_accA[d + 1], a.y);
        atomicAdd(&g_accA[d + 2], a.z); atomicAdd(&g_accA[d + 3], a.w);
        atomicAdd(&g_accB[d + 0], b.x); atomicAdd(&g_accB[d + 1], b.y);
        atomicAdd(&g_accB[d + 2], b.z); atomicAdd(&g_accB[d + 3], b.w);
    }
}

// ---------------- K6: logits + exp + block-aggregated sumexp ---------------------
// 2 rows per warp, 16 rows/block, grid 3125. One-shot LDG.128 on W.
__global__ void k6_logits(const float* __restrict__ W, const float* __restrict__ b,
                          float* __restrict__ out) {
    __shared__ float s_feat[D];
    __shared__ float s_p[8];
    int t = threadIdx.x;                      // 256
    {
        float a  = 1.0f - (float)t * (1.0f / D);
        float be = 2.0f * (float)t * (1.0f / D) - 1.0f;
        float invS = 1.0f / g_sumw;
        s_feat[t] = (a * g_accA[t] + be * g_accB[t] + g_wte1[t]) * invS + g_qemb[t];
    }
    __syncthreads();
    int warp = t >> 5, lane = t & 31;
    int vbase = blockIdx.x * 16 + warp * 2;
    const float4* rowA = (const float4*)(W + (size_t)vbase * D);
    const float4* rowB = (const float4*)(W + (size_t)(vbase + 1) * D);
    float4 xa0 = __ldg(&rowA[lane]);
    float4 xa1 = __ldg(&rowA[lane + 32]);
    float4 xb0 = __ldg(&rowB[lane]);
    float4 xb1 = __ldg(&rowB[lane + 32]);
    const float4* sf = (const float4*)s_feat;
    float4 f0 = sf[lane], f1 = sf[lane + 32];
    float s0 = dot8(xa0, xa1, f0, f1);
    float s1 = dot8(xb0, xb1, f0, f1);
    s0 = warp_sum(s0); s1 = warp_sum(s1);
    float p_sum = 0.0f;
    if (lane == 0) {
        float p0 = expf(s0 + __ldg(&b[vbase]));
        float p1 = expf(s1 + __ldg(&b[vbase + 1]));
        out[vbase] = p0;                      // unnormalized
        out[vbase + 1] = p1;
        p_sum = p0 + p1;
        s_p[warp] = p_sum;
    }
    __syncthreads();
    if (t < 8) {
        float x = s_p[t];
        #pragma unroll
        for (int o = 4; o > 0; o >>= 1) x += __shfl_xor_sync(0xffu, x, o);
        if (t == 0) atomicAdd(&g_sumexp, x);
    }
}

// ---------------- K7: normalize output -------------------------------------------
__global__ void k7_scale(float* __restrict__ out) {
    int i = blockIdx.x * blockDim.x + threadIdx.x;
    float inv = 1.0f / g_sumexp;
    if (i < VOCAB) out[i] *= inv;
}

// ---------------- launch ---------------------------------------------------------
extern "C" void kernel_launch(void* const* d_in, const int* in_sizes, int n_in,
                              void* d_out, int out_size) {
    const int*   evidence = (const int*)  d_in[0];
    const int*   question = (const int*)  d_in[1];
    const float* q_table  = (const float*)d_in[2];
    const float* e_table  = (const float*)d_in[3];
    const float* te1      = (const float*)d_in[4];
    const float* te2      = (const float*)d_in[5];
    const float* W        = (const float*)d_in[6];
    const float* b        = (const float*)d_in[7];
    float* out = (float*)d_out;

    k1_qemb<<<1, 256>>>(question, q_table);
    k2_uw<<<VOCAB / 16, 256>>>(q_table);
    k34_weights<<<K34_BLOCKS, 256>>>(evidence, te2, te1);
    k5_etable<<<K5_BLOCKS, 256>>>(e_table);
    k6_logits<<<VOCAB / 16, 256>>>(W, b, out);
    k7_scale<<<(VOCAB + 255) / 256, 256>>>(out);
}

// round 13
// speedup vs baseline: 2.6786x; 2.6786x over previous
#include <cuda_runtime.h>
#include <cuda_bf16.h>

#define VOCAB 50000
#define D 256
#define E 20000
#define L 20

// ---------------- scratch (static device globals; no allocation) ----------------
__device__ float g_qemb[D];
__device__ float g_g0[D];        // alpha(d) * qemb[d]
__device__ float g_g1[D];        // beta(d)  * qemb[d]
__device__ float g_u[VOCAB];
__device__ float g_w[VOCAB];
__device__ __align__(16) float g_A[VOCAB];  // unnormalized attention mass per vocab id
__device__ __align__(16) float g_B[VOCAB];  // same, weighted by l/L
__device__ float g_accA[D];
__device__ float g_accB[D];
__device__ float g_wte1[D];
__device__ float g_sumw;         // sum of exp(scores)
__device__ float g_sumexp;       // sum of exp(logits)

__device__ __forceinline__ float warp_sum(float v) {
    #pragma unroll
    for (int o = 16; o > 0; o >>= 1) v += __shfl_xor_sync(0xffffffffu, v, o);
    return v;
}

__device__ __forceinline__ float dot8(float4 x0, float4 x1, float4 c0, float4 c1) {
    return x0.x*c0.x + x0.y*c0.y + x0.z*c0.z + x0.w*c0.w
         + x1.x*c1.x + x1.y*c1.y + x1.z*c1.z + x1.w*c1.w;
}

// ---------------- K1: q_emb + derived vectors, zero accumulators ----------------
__global__ void k1_qemb(const int* __restrict__ question,
                        const float* __restrict__ q_table) {
    int d = threadIdx.x;                         // 256 threads
    float a  = 1.0f - (float)d * (1.0f / D);
    float be = 2.0f * (float)d * (1.0f / D) - 1.0f;
    float s = 0.0f;
    #pragma unroll
    for (int l = 0; l < L; ++l) {
        int v = question[l];
        float pe = a + ((float)l * (1.0f / L)) * be;
        s += __ldg(&q_table[(size_t)v * D + d]) * pe;
    }
    g_qemb[d] = s;
    g_g0[d] = a * s;
    g_g1[d] = be * s;
    g_accA[d] = 0.0f; g_accB[d] = 0.0f; g_wte1[d] = 0.0f;
    if (d == 0) { g_sumw = 0.0f; g_sumexp = 0.0f; }
}

// ---------------- K2: u[v], w[v] over q_table; zero A/B --------------------------
// 2 rows per warp, 16 rows/block, grid 3125. 4 independent one-shot LDG.128.
__global__ void k2_uw(const float* __restrict__ q_table) {
    __shared__ float4 s0[64], s1[64];
    int t = threadIdx.x;                      // 256
    if (t < 64) {
        s0[t] = ((const float4*)g_g0)[t];
        s1[t] = ((const float4*)g_g1)[t];
    }
    __syncthreads();
    int warp = t >> 5, lane = t & 31;
    int vbase = blockIdx.x * 16 + warp * 2;
    const float4* rowA = (const float4*)(q_table + (size_t)vbase * D);
    const float4* rowB = (const float4*)(q_table + (size_t)(vbase + 1) * D);
    float4 xa0 = __ldg(&rowA[lane]);
    float4 xa1 = __ldg(&rowA[lane + 32]);
    float4 xb0 = __ldg(&rowB[lane]);
    float4 xb1 = __ldg(&rowB[lane + 32]);
    float4 c0 = s0[lane], c1 = s0[lane + 32];
    float4 d0 = s1[lane], d1 = s1[lane + 32];
    float u0 = dot8(xa0, xa1, c0, c1);
    float w0 = dot8(xa0, xa1, d0, d1);
    float u1 = dot8(xb0, xb1, c0, c1);
    float w1 = dot8(xb0, xb1, d0, d1);
    u0 = warp_sum(u0); w0 = warp_sum(w0);
    u1 = warp_sum(u1); w1 = warp_sum(w1);
    if (lane == 0) {
        g_u[vbase] = u0;     g_w[vbase] = w0;
        g_u[vbase + 1] = u1; g_w[vbase + 1] = w1;
    }
    if (t < 16) { g_A[blockIdx.x * 16 + t] = 0.0f; g_B[blockIdx.x * 16 + t] = 0.0f; }
}

// ---------------- K34: fused scores + exp + A/B scatter + weights@te1 ------------
#define K34_CHUNK  32
#define K34_BLOCKS (E / K34_CHUNK)    // 625
__global__ void k34_weights(const int* __restrict__ evidence,
                            const float* __restrict__ te2,
                            const float* __restrict__ te1) {
    __shared__ float4 sq[64];
    __shared__ float s_w[K34_CHUNK];
    int t = threadIdx.x;                      // 256
    int warp = t >> 5, lane = t & 31;
    if (t < 64) sq[t] = ((const float4*)g_qemb)[t];
    __syncthreads();
    int e0 = blockIdx.x * K34_CHUNK;
    float4 q0 = sq[lane], q1 = sq[lane + 32];
    float part[4];
    #pragma unroll
    for (int r = 0; r < 4; ++r) {
        int e = e0 + warp * 4 + r;
        float p = 0.0f;
        if (lane < L) {
            int v = __ldg(&evidence[e * L + lane]);
            p = g_u[v] + ((float)lane * (1.0f / L)) * g_w[v];
        }
        const float4* row = (const float4*)(te2 + (size_t)e * D);
        float4 x0 = __ldg(&row[lane]);
        float4 x1 = __ldg(&row[lane + 32]);
        part[r] = p + dot8(x0, x1, q0, q1);
    }
    #pragma unroll
    for (int r = 0; r < 4; ++r) part[r] = warp_sum(part[r]);
    if (lane == 0) {
        #pragma unroll
        for (int r = 0; r < 4; ++r) s_w[warp * 4 + r] = part[r];
    }
    __syncthreads();
    if (t < 32) {
        float w = expf(s_w[t]);
        s_w[t] = w;
        float s = warp_sum(w);
        if (t == 0) atomicAdd(&g_sumw, s);
    }
    __syncthreads();
    for (int i = t; i < K34_CHUNK * L; i += 256) {
        int el = i / L;
        int l  = i - el * L;
        int v  = __ldg(&evidence[(e0 + el) * L + l]);
        float w = s_w[el];
        atomicAdd(&g_A[v], w);
        atomicAdd(&g_B[v], w * ((float)l * (1.0f / L)));
    }
    int d = t;
    float acc = 0.0f;
    #pragma unroll 8
    for (int el = 0; el < K34_CHUNK; ++el)
        acc += s_w[el] * __ldg(&te1[(size_t)(e0 + el) * D + d]);
    atomicAdd(&g_wte1[d], acc);
}

// ---------------- K5: accA/accB = A@e_table, B@e_table ---------------------------
// r10 grid-stride structure + cross-iteration software prefetch: next octet's
// 8 stream values + coeff float4s are loaded into separate registers whose
// uses are beyond the loop backedge, so ptxas cannot sink them -> MLP ~ 8.
#define K5_GRID 1184
__global__ void k5_etable(const float* __restrict__ e_table) {
    int t = threadIdx.x;                      // 256 (= column)
    const int nocts = VOCAB / 8;              // 6250
    float a = 0.0f, b = 0.0f;
    int q = blockIdx.x;                       // always < nocts (1184 < 6250)
    float x[8];
    float4 A0, A1, B0, B1;
    {
        const float* base = e_table + (size_t)q * 8 * D + t;
        #pragma unroll
        for (int k = 0; k < 8; ++k) x[k] = __ldg(base + k * D);
        A0 = __ldg((const float4*)&g_A[q * 8]);
        A1 = __ldg((const float4*)&g_A[q * 8 + 4]);
        B0 = __ldg((const float4*)&g_B[q * 8]);
        B1 = __ldg((const float4*)&g_B[q * 8 + 4]);
    }
    while (true) {
        int qn = q + K5_GRID;
        bool more = qn < nocts;
        float xn[8];
        float4 An0, An1, Bn0, Bn1;
        if (more) {
            const float* base = e_table + (size_t)qn * 8 * D + t;
            #pragma unroll
            for (int k = 0; k < 8; ++k) xn[k] = __ldg(base + k * D);
            An0 = __ldg((const float4*)&g_A[qn * 8]);
            An1 = __ldg((const float4*)&g_A[qn * 8 + 4]);
            Bn0 = __ldg((const float4*)&g_B[qn * 8]);
            Bn1 = __ldg((const float4*)&g_B[qn * 8 + 4]);
        }
        a += A0.x * x[0] + A0.y * x[1] + A0.z * x[2] + A0.w * x[3]
           + A1.x * x[4] + A1.y * x[5] + A1.z * x[6] + A1.w * x[7];
        b += B0.x * x[0] + B0.y * x[1] + B0.z * x[2] + B0.w * x[3]
           + B1.x * x[4] + B1.y * x[5] + B1.z * x[6] + B1.w * x[7];
        if (!more) break;
        #pragma unroll
        for (int k = 0; k < 8; ++k) x[k] = xn[k];
        A0 = An0; A1 = An1; B0 = Bn0; B1 = Bn1;
        q = qn;
    }
    atomicAdd(&g_accA[t], a);
    atomicAdd(&g_accB[t], b);
}

// ---------------- K6: logits + exp + block-aggregated sumexp ---------------------
// 2 rows per warp, 16 rows/block, grid 3125. One-shot LDG.128 on W.
__global__ void k6_logits(const float* __restrict__ W, const float* __restrict__ b,
                          float* __restrict__ out) {
    __shared__ float s_feat[D];
    __shared__ float s_p[8];
    int t = threadIdx.x;                      // 256
    {
        float a  = 1.0f - (float)t * (1.0f / D);
        float be = 2.0f * (float)t * (1.0f / D) - 1.0f;
        float invS = 1.0f / g_sumw;
        s_feat[t] = (a * g_accA[t] + be * g_accB[t] + g_wte1[t]) * invS + g_qemb[t];
    }
    __syncthreads();
    int warp = t >> 5, lane = t & 31;
    int vbase = blockIdx.x * 16 + warp * 2;
    const float4* rowA = (const float4*)(W + (size_t)vbase * D);
    const float4* rowB = (const float4*)(W + (size_t)(vbase + 1) * D);
    float4 xa0 = __ldg(&rowA[lane]);
    float4 xa1 = __ldg(&rowA[lane + 32]);
    float4 xb0 = __ldg(&rowB[lane]);
    float4 xb1 = __ldg(&rowB[lane + 32]);
    const float4* sf = (const float4*)s_feat;
    float4 f0 = sf[lane], f1 = sf[lane + 32];
    float s0 = dot8(xa0, xa1, f0, f1);
    float s1 = dot8(xb0, xb1, f0, f1);
    s0 = warp_sum(s0); s1 = warp_sum(s1);
    float p_sum = 0.0f;
    if (lane == 0) {
        float p0 = expf(s0 + __ldg(&b[vbase]));
        float p1 = expf(s1 + __ldg(&b[vbase + 1]));
        out[vbase] = p0;                      // unnormalized
        out[vbase + 1] = p1;
        p_sum = p0 + p1;
        s_p[warp] = p_sum;
    }
    __syncthreads();
    if (t < 8) {
        float x = s_p[t];
        #pragma unroll
        for (int o = 4; o > 0; o >>= 1) x += __shfl_xor_sync(0xffu, x, o);
        if (t == 0) atomicAdd(&g_sumexp, x);
    }
}

// ---------------- K7: normalize output (float4) ----------------------------------
__global__ void k7_scale(float* __restrict__ out) {
    int i = blockIdx.x * blockDim.x + threadIdx.x;   // VOCAB/4 = 12500 float4
    float inv = 1.0f / g_sumexp;
    if (i < VOCAB / 4) {
        float4 v = ((const float4*)out)[i];
        v.x *= inv; v.y *= inv; v.z *= inv; v.w *= inv;
        ((float4*)out)[i] = v;
    }
}

// ---------------- launch ---------------------------------------------------------
extern "C" void kernel_launch(void* const* d_in, const int* in_sizes, int n_in,
                              void* d_out, int out_size) {
    const int*   evidence = (const int*)  d_in[0];
    const int*   question = (const int*)  d_in[1];
    const float* q_table  = (const float*)d_in[2];
    const float* e_table  = (const float*)d_in[3];
    const float* te1      = (const float*)d_in[4];
    const float* te2      = (const float*)d_in[5];
    const float* W        = (const float*)d_in[6];
    const float* b        = (const float*)d_in[7];
    float* out = (float*)d_out;

    k1_qemb<<<1, 256>>>(question, q_table);
    k2_uw<<<VOCAB / 16, 256>>>(q_table);
    k34_weights<<<K34_BLOCKS, 256>>>(evidence, te2, te1);
    k5_etable<<<K5_GRID, 256>>>(e_table);
    k6_logits<<<VOCAB / 16, 256>>>(W, b, out);
    k7_scale<<<(VOCAB / 4 + 255) / 256, 256>>>(out);
}

// round 15
// speedup vs baseline: 2.8502x; 1.0640x over previous
#include <cuda_runtime.h>
#include <cuda_bf16.h>

#define VOCAB 50000
#define D 256
#define E 20000
#define L 20

// ---------------- scratch (static device globals; no allocation) ----------------
__device__ float g_qemb[D];
__device__ float g_g0[D];
__device__ float g_g1[D];
__device__ float g_u[VOCAB];
__device__ float g_w[VOCAB];
__device__ __align__(16) float g_A[VOCAB];
__device__ __align__(16) float g_B[VOCAB];
__device__ float g_accA[D];
__device__ float g_accB[D];
__device__ float g_wte1[D];
__device__ float g_sumw;
__device__ float g_sumexp;

__device__ __forceinline__ float warp_sum(float v) {
    #pragma unroll
    for (int o = 16; o > 0; o >>= 1) v += __shfl_xor_sync(0xffffffffu, v, o);
    return v;
}

__device__ __forceinline__ float dot8(float4 x0, float4 x1, float4 c0, float4 c1) {
    return x0.x*c0.x + x0.y*c0.y + x0.z*c0.z + x0.w*c0.w
         + x1.x*c1.x + x1.y*c1.y + x1.z*c1.z + x1.w*c1.w;
}

// ---- bulk-TMA + mbarrier helpers (CUTLASS-exact instruction forms) --------------
__device__ __forceinline__ unsigned smem_u32(const void* p) {
    return (unsigned)__cvta_generic_to_shared(p);
}
__device__ __forceinline__ void mbar_init(unsigned mbar, unsigned cnt) {
    asm volatile("mbarrier.init.shared::cta.b64 [%0], %1;" :: "r"(mbar), "r"(cnt) : "memory");
}
__device__ __forceinline__ void mbar_expect_tx(unsigned mbar, unsigned bytes) {
    asm volatile("mbarrier.arrive.expect_tx.shared::cta.b64 _, [%0], %1;"
                 :: "r"(mbar), "r"(bytes) : "memory");
}
__device__ __forceinline__ void tma_bulk_g2s(unsigned sdst, const void* gsrc,
                                             unsigned bytes, unsigned mbar) {
    asm volatile("cp.async.bulk.shared::cluster.global.mbarrier::complete_tx::bytes "
                 "[%0], [%1], %2, [%3];"
                 :: "r"(sdst), "l"(gsrc), "r"(bytes), "r"(mbar) : "memory");
}
__device__ __forceinline__ void mbar_wait(unsigned mbar, unsigned parity) {
    asm volatile("{\n\t"
                 ".reg .pred P;\n\t"
                 "WAIT%=:\n\t"
                 "mbarrier.try_wait.parity.shared::cta.b64 P, [%0], %1;\n\t"
                 "@!P bra WAIT%=;\n\t"
                 "}" :: "r"(mbar), "r"(parity) : "memory");
}

#define TGRID   592                  // ~4 CTAs/SM
#define TCR     16                   // rows per chunk (16KB)
#define TCB     (TCR * D * 4)        // bytes per chunk
#define TNCH    (VOCAB / TCR)        // 3125 chunks
#define NST     2                    // pipeline stages (32KB smem)

// ---------------- K1: q_emb + derived vectors, zero accumulators ----------------
__global__ void k1_qemb(const int* __restrict__ question,
                        const float* __restrict__ q_table) {
    int d = threadIdx.x;                         // 256 threads
    float a  = 1.0f - (float)d * (1.0f / D);
    float be = 2.0f * (float)d * (1.0f / D) - 1.0f;
    float s = 0.0f;
    #pragma unroll
    for (int l = 0; l < L; ++l) {
        int v = question[l];
        float pe = a + ((float)l * (1.0f / L)) * be;
        s += __ldg(&q_table[(size_t)v * D + d]) * pe;
    }
    g_qemb[d] = s;
    g_g0[d] = a * s;
    g_g1[d] = be * s;
    g_accA[d] = 0.0f; g_accB[d] = 0.0f; g_wte1[d] = 0.0f;
    if (d == 0) { g_sumw = 0.0f; g_sumexp = 0.0f; }
}

// ---------------- K2: u[v], w[v] over q_table; zero A/B --------------------------
__global__ void k2_uw(const float* __restrict__ q_table) {
    __shared__ float4 s0[64], s1[64];
    int t = threadIdx.x;                      // 256
    if (t < 64) {
        s0[t] = ((const float4*)g_g0)[t];
        s1[t] = ((const float4*)g_g1)[t];
    }
    __syncthreads();
    int warp = t >> 5, lane = t & 31;
    int vbase = blockIdx.x * 16 + warp * 2;
    const float4* rowA = (const float4*)(q_table + (size_t)vbase * D);
    const float4* rowB = (const float4*)(q_table + (size_t)(vbase + 1) * D);
    float4 xa0 = __ldg(&rowA[lane]);
    float4 xa1 = __ldg(&rowA[lane + 32]);
    float4 xb0 = __ldg(&rowB[lane]);
    float4 xb1 = __ldg(&rowB[lane + 32]);
    float4 c0 = s0[lane], c1 = s0[lane + 32];
    float4 d0 = s1[lane], d1 = s1[lane + 32];
    float u0 = dot8(xa0, xa1, c0, c1);
    float w0 = dot8(xa0, xa1, d0, d1);
    float u1 = dot8(xb0, xb1, c0, c1);
    float w1 = dot8(xb0, xb1, d0, d1);
    u0 = warp_sum(u0); w0 = warp_sum(w0);
    u1 = warp_sum(u1); w1 = warp_sum(w1);
    if (lane == 0) {
        g_u[vbase] = u0;     g_w[vbase] = w0;
        g_u[vbase + 1] = u1; g_w[vbase + 1] = w1;
    }
    if (t < 16) { g_A[blockIdx.x * 16 + t] = 0.0f; g_B[blockIdx.x * 16 + t] = 0.0f; }
}

// ---------------- K34: fused scores + exp + A/B scatter + weights@te1 ------------
#define K34_CHUNK  32
#define K34_BLOCKS (E / K34_CHUNK)    // 625
__global__ void k34_weights(const int* __restrict__ evidence,
                            const float* __restrict__ te2,
                            const float* __restrict__ te1) {
    __shared__ float4 sq[64];
    __shared__ float s_w[K34_CHUNK];
    int t = threadIdx.x;                      // 256
    int warp = t >> 5, lane = t & 31;
    if (t < 64) sq[t] = ((const float4*)g_qemb)[t];
    __syncthreads();
    int e0 = blockIdx.x * K34_CHUNK;
    float4 q0 = sq[lane], q1 = sq[lane + 32];
    float part[4];
    #pragma unroll
    for (int r = 0; r < 4; ++r) {
        int e = e0 + warp * 4 + r;
        float p = 0.0f;
        if (lane < L) {
            int v = __ldg(&evidence[e * L + lane]);
            p = g_u[v] + ((float)lane * (1.0f / L)) * g_w[v];
        }
        const float4* row = (const float4*)(te2 + (size_t)e * D);
        float4 x0 = __ldg(&row[lane]);
        float4 x1 = __ldg(&row[lane + 32]);
        part[r] = p + dot8(x0, x1, q0, q1);
    }
    #pragma unroll
    for (int r = 0; r < 4; ++r) part[r] = warp_sum(part[r]);
    if (lane == 0) {
        #pragma unroll
        for (int r = 0; r < 4; ++r) s_w[warp * 4 + r] = part[r];
    }
    __syncthreads();
    if (t < 32) {
        float w = expf(s_w[t]);
        s_w[t] = w;
        float s = warp_sum(w);
        if (t == 0) atomicAdd(&g_sumw, s);
    }
    __syncthreads();
    for (int i = t; i < K34_CHUNK * L; i += 256) {
        int el = i / L;
        int l  = i - el * L;
        int v  = __ldg(&evidence[(e0 + el) * L + l]);
        float w = s_w[el];
        atomicAdd(&g_A[v], w);
        atomicAdd(&g_B[v], w * ((float)l * (1.0f / L)));
    }
    int d = t;
    float acc = 0.0f;
    #pragma unroll 8
    for (int el = 0; el < K34_CHUNK; ++el)
        acc += s_w[el] * __ldg(&te1[(size_t)(e0 + el) * D + d]);
    atomicAdd(&g_wte1[d], acc);
}

// ---------------- K5: accA/accB = A@e_table, B@e_table (bulk-TMA, 2 stages) ------
__global__ void k5_etable(const float* __restrict__ e_table) {
    __shared__ __align__(128) float buf[NST][TCR * D];
    __shared__ __align__(8) unsigned long long mbar_s[NST];
    int t = threadIdx.x;                      // 256 (= column)
    unsigned mb0 = smem_u32(&mbar_s[0]);
    unsigned mb1 = smem_u32(&mbar_s[1]);
    if (t == 0) { mbar_init(mb0, 1); mbar_init(mb1, 1); }
    __syncthreads();
    if (t == 0) {
        #pragma unroll
        for (int s = 0; s < NST; ++s) {
            int c = blockIdx.x + s * TGRID;
            if (c < TNCH) {
                unsigned mb = s ? mb1 : mb0;
                mbar_expect_tx(mb, TCB);
                tma_bulk_g2s(smem_u32(buf[s]), e_table + (size_t)c * TCR * D, TCB, mb);
            }
        }
    }
    float a = 0.0f, b = 0.0f;
    int i = 0;
    for (int c = blockIdx.x; c < TNCH; c += TGRID, ++i) {
        int stage = i & 1;
        int parity = (i >> 1) & 1;
        unsigned mb = stage ? mb1 : mb0;
        int v0 = c * TCR;
        // coeffs (L2-resident) overlap the barrier wait
        float4 A0 = __ldg((const float4*)&g_A[v0]);
        float4 A1 = __ldg((const float4*)&g_A[v0 + 4]);
        float4 A2 = __ldg((const float4*)&g_A[v0 + 8]);
        float4 A3 = __ldg((const float4*)&g_A[v0 + 12]);
        float4 B0 = __ldg((const float4*)&g_B[v0]);
        float4 B1 = __ldg((const float4*)&g_B[v0 + 4]);
        float4 B2 = __ldg((const float4*)&g_B[v0 + 8]);
        float4 B3 = __ldg((const float4*)&g_B[v0 + 12]);
        mbar_wait(mb, parity);
        const float* base = buf[stage] + t;
        float x0  = base[0 * D],  x1  = base[1 * D],  x2  = base[2 * D],  x3  = base[3 * D];
        float x4  = base[4 * D],  x5  = base[5 * D],  x6  = base[6 * D],  x7  = base[7 * D];
        float x8  = base[8 * D],  x9  = base[9 * D],  x10 = base[10 * D], x11 = base[11 * D];
        float x12 = base[12 * D], x13 = base[13 * D], x14 = base[14 * D], x15 = base[15 * D];
        a += A0.x*x0 + A0.y*x1 + A0.z*x2 + A0.w*x3
           + A1.x*x4 + A1.y*x5 + A1.z*x6 + A1.w*x7
           + A2.x*x8 + A2.y*x9 + A2.z*x10 + A2.w*x11
           + A3.x*x12 + A3.y*x13 + A3.z*x14 + A3.w*x15;
        b += B0.x*x0 + B0.y*x1 + B0.z*x2 + B0.w*x3
           + B1.x*x4 + B1.y*x5 + B1.z*x6 + B1.w*x7
           + B2.x*x8 + B2.y*x9 + B2.z*x10 + B2.w*x11
           + B3.x*x12 + B3.y*x13 + B3.z*x14 + B3.w*x15;
        __syncthreads();                      // all reads done before refill
        if (t == 0) {
            int cn = c + NST * TGRID;
            if (cn < TNCH) {
                mbar_expect_tx(mb, TCB);
                tma_bulk_g2s(smem_u32(buf[stage]), e_table + (size_t)cn * TCR * D, TCB, mb);
            }
        }
    }
    atomicAdd(&g_accA[t], a);
    atomicAdd(&g_accB[t], b);
}

// ---------------- K6: logits + exp + sumexp (bulk-TMA over W, 2 stages) ----------
__global__ void k6_logits(const float* __restrict__ W, const float* __restrict__ bb,
                          float* __restrict__ out) {
    __shared__ __align__(128) float buf[NST][TCR * D];
    __shared__ __align__(8) unsigned long long mbar_s[NST];
    __shared__ float s_feat[D];
    __shared__ float s_p[8];
    int t = threadIdx.x;                      // 256
    int warp = t >> 5, lane = t & 31;
    unsigned mb0 = smem_u32(&mbar_s[0]);
    unsigned mb1 = smem_u32(&mbar_s[1]);
    if (t == 0) { mbar_init(mb0, 1); mbar_init(mb1, 1); }
    {
        float a  = 1.0f - (float)t * (1.0f / D);
        float be = 2.0f * (float)t * (1.0f / D) - 1.0f;
        float invS = 1.0f / g_sumw;
        s_feat[t] = (a * g_accA[t] + be * g_accB[t] + g_wte1[t]) * invS + g_qemb[t];
    }
    __syncthreads();
    if (t == 0) {
        #pragma unroll
        for (int s = 0; s < NST; ++s) {
            int c = blockIdx.x + s * TGRID;
            if (c < TNCH) {
                unsigned mb = s ? mb1 : mb0;
                mbar_expect_tx(mb, TCB);
                tma_bulk_g2s(smem_u32(buf[s]), W + (size_t)c * TCR * D, TCB, mb);
            }
        }
    }
    const float4* sf = (const float4*)s_feat;
    float4 f0 = sf[lane], f1 = sf[lane + 32];
    float p_sum = 0.0f;
    int i = 0;
    for (int c = blockIdx.x; c < TNCH; c += TGRID, ++i) {
        int stage = i & 1;
        int parity = (i >> 1) & 1;
        unsigned mb = stage ? mb1 : mb0;
        int vbase = c * TCR + warp * 2;
        float bias0 = __ldg(&bb[vbase]);
        float bias1 = __ldg(&bb[vbase + 1]);
        mbar_wait(mb, parity);
        const float4* bf = (const float4*)buf[stage];
        float4 xa0 = bf[(warp * 2) * 64 + lane];
        float4 xa1 = bf[(warp * 2) * 64 + lane + 32];
        float4 xb0 = bf[(warp * 2 + 1) * 64 + lane];
        float4 xb1 = bf[(warp * 2 + 1) * 64 + lane + 32];
        float s0 = dot8(xa0, xa1, f0, f1);
        float s1 = dot8(xb0, xb1, f0, f1);
        s0 = warp_sum(s0); s1 = warp_sum(s1);
        if (lane == 0) {
            float p0 = expf(s0 + bias0);
            float p1 = expf(s1 + bias1);
            out[vbase] = p0;                  // unnormalized
            out[vbase + 1] = p1;
            p_sum += p0 + p1;
        }
        __syncthreads();                      // all reads done before refill
        if (t == 0) {
            int cn = c + NST * TGRID;
            if (cn < TNCH) {
                mbar_expect_tx(mb, TCB);
                tma_bulk_g2s(smem_u32(buf[stage]), W + (size_t)cn * TCR * D, TCB, mb);
            }
        }
    }
    if (lane == 0) s_p[warp] = p_sum;
    __syncthreads();
    if (t < 8) {
        float x = s_p[t];
        #pragma unroll
        for (int o = 4; o > 0; o >>= 1) x += __shfl_xor_sync(0xffu, x, o);
        if (t == 0) atomicAdd(&g_sumexp, x);
    }
}

// ---------------- K7: normalize output (float4) ----------------------------------
__global__ void k7_scale(float* __restrict__ out) {
    int i = blockIdx.x * blockDim.x + threadIdx.x;   // VOCAB/4 = 12500 float4
    float inv = 1.0f / g_sumexp;
    if (i < VOCAB / 4) {
        float4 v = ((const float4*)out)[i];
        v.x *= inv; v.y *= inv; v.z *= inv; v.w *= inv;
        ((float4*)out)[i] = v;
    }
}

// ---------------- launch ---------------------------------------------------------
extern "C" void kernel_launch(void* const* d_in, const int* in_sizes, int n_in,
                              void* d_out, int out_size) {
    const int*   evidence = (const int*)  d_in[0];
    const int*   question = (const int*)  d_in[1];
    const float* q_table  = (const float*)d_in[2];
    const float* e_table  = (const float*)d_in[3];
    const float* te1      = (const float*)d_in[4];
    const float* te2      = (const float*)d_in[5];
    const float* W        = (const float*)d_in[6];
    const float* b        = (const float*)d_in[7];
    float* out = (float*)d_out;

    k1_qemb<<<1, 256>>>(question, q_table);
    k2_uw<<<VOCAB / 16, 256>>>(q_table);
    k34_weights<<<K34_BLOCKS, 256>>>(evidence, te2, te1);
    k5_etable<<<TGRID, 256>>>(e_table);
    k6_logits<<<TGRID, 256>>>(W, b, out);
    k7_scale<<<(VOCAB / 4 + 255) / 256, 256>>>(out);
}